// round 15
// baseline (speedup 1.0000x reference)
#include <cuda_runtime.h>
#include <cuda_bf16.h>

// PointPWC loss, B=1, N=8192.
// total = 0.02*chamfer + 0.006*curv + 0.01*smooth
//
// R13 (re-run; previous attempt hit a container infra failure):
//  Two-pass windowed kNN — selection decoupled from identification.
//  Pass 1: branchless distance-only top-K (FMNMX bubble, no ids, no branches)
//          over the pruned x-sorted window (R11 machinery: bucket sort, block
//          slab, per-tile block-uniform vote with BW slack).
//  Pass 2: rescan the recorded window; member iff dm <= kth (identical FMA
//          sequence both passes -> deterministic; ties measure-zero). Rare
//          branch stores (dist,id) into the SAME per-side scratch layout the
//          proven R11 consume kernels read. Near-to-far order + cnt<K guard
//          keeps pad sentinels from displacing real members on short sides.
//  Downstream merge/consume unchanged from R11. Finalize folded into
//  cross_consume via fence+ticket.

#define MAXN  8192
#define KNN   10
#define KNN5  5
#define TPB   256
#define PAD   256
#define PADN  (MAXN + 2 * PAD)
#define NB    1024
#define XMIN  (-8.0f)
#define BSCALE 64.0f           // NB / 16
#define BW    0.015625f        // 16 / NB

__device__ float4 g_pc1[MAXN], g_pc2[MAXN], g_warp[MAXN], g_flow[MAXN];
__device__ float4 g_p1s[PADN], g_p2s[PADN], g_ws[PADN];     // sorted + pads
__device__ float4 g_flow1s[PADN], g_warp1s[PADN];           // pc1-sorted order
__device__ int    g_idx1[MAXN];   // pc1-sorted -> orig
__device__ int    g_idxw[MAXN];   // warp-sorted -> orig
__device__ float4 g_c2s[PADN];    // curvature of pc2, padded sorted pos
__device__ float4 g_moved[MAXN];  // moved curvature, orig order
// i-major partials: ((r*MAXN + i)*2 + dir)*KNN + t
__device__ float  g_pd[3 * MAXN * 2 * KNN];
__device__ int    g_pi[3 * MAXN * 2 * KNN];
__device__ float  g_pmin[MAXN * 2];
__device__ int    g_bins[3 * NB];
__device__ int    g_ticket;
__device__ double g_acc[4];  // 0: chamfer fwd, 1: chamfer bwd, 2: smooth, 3: curv

__device__ __forceinline__ int bucketf(float x) {
    int b = (int)((x - XMIN) * BSCALE);
    return min(max(b, 0), NB - 1);
}

__device__ __forceinline__ double warp_red(double v) {
    #pragma unroll
    for (int o = 16; o > 0; o >>= 1)
        v += __shfl_down_sync(0xffffffffu, v, o);
    return v;
}

__global__ void zero_kernel() {
    int gid = blockIdx.x * blockDim.x + threadIdx.x;
    if (gid < 3 * NB) g_bins[gid] = 0;
    if (gid < 4) g_acc[gid] = 0.0;
    if (gid == 4) g_ticket = 0;
    if (gid < PAD) {
        float4 lp = make_float4(-1e18f, 0.f, 0.f, 3.4e38f);
        float4 rp = make_float4( 1e18f, 0.f, 0.f, 3.4e38f);
        g_p1s[gid] = lp; g_p1s[PAD + MAXN + gid] = rp;
        g_p2s[gid] = lp; g_p2s[PAD + MAXN + gid] = rp;
        g_ws[gid]  = lp; g_ws[PAD + MAXN + gid]  = rp;
    }
}

__global__ void prep_kernel(const float* __restrict__ pred,
                            const float* __restrict__ gt,
                            const float* __restrict__ coords, int n) {
    int i = blockIdx.x * blockDim.x + threadIdx.x;
    if (i >= n) return;
    float cx = coords[3 * i + 0], cy = coords[3 * i + 1], cz = coords[3 * i + 2];
    float gx = gt[3 * i + 0],     gy = gt[3 * i + 1],     gz = gt[3 * i + 2];
    float fx = pred[3 * i + 0],   fy = pred[3 * i + 1],   fz = pred[3 * i + 2];
    float p2x = cx + gx, p2y = cy + gy, p2z = cz + gz;
    float wx  = cx + fx, wy  = cy + fy, wz  = cz + fz;
    g_pc1[i]  = make_float4(cx, cy, cz, cx * cx + cy * cy + cz * cz);
    g_pc2[i]  = make_float4(p2x, p2y, p2z, p2x * p2x + p2y * p2y + p2z * p2z);
    g_warp[i] = make_float4(wx, wy, wz, wx * wx + wy * wy + wz * wz);
    g_flow[i] = make_float4(fx, fy, fz, 0.f);
    atomicAdd(&g_bins[bucketf(cx)], 1);
    atomicAdd(&g_bins[NB + bucketf(p2x)], 1);
    atomicAdd(&g_bins[2 * NB + bucketf(wx)], 1);
}

__global__ void scan_kernel() {
    __shared__ int s[NB];
    int t = threadIdx.x;
    for (int h = 0; h < 3; h++) {
        int orig = g_bins[h * NB + t];
        s[t] = orig;
        __syncthreads();
        for (int o = 1; o < NB; o <<= 1) {
            int v = (t >= o) ? s[t - o] : 0;
            __syncthreads();
            s[t] += v;
            __syncthreads();
        }
        g_bins[h * NB + t] = s[t] - orig;  // exclusive start
        __syncthreads();
    }
}

// after this kernel g_bins holds bucket END offsets
__global__ void scatter_kernel(int n) {
    int i = blockIdx.x * blockDim.x + threadIdx.x;
    if (i >= n) return;
    float4 p1 = g_pc1[i];
    int s1 = atomicAdd(&g_bins[bucketf(p1.x)], 1);
    g_p1s[PAD + s1] = p1;
    g_flow1s[PAD + s1] = g_flow[i];
    g_warp1s[PAD + s1] = g_warp[i];
    g_idx1[s1] = i;
    float4 p2 = g_pc2[i];
    int s2 = atomicAdd(&g_bins[NB + bucketf(p2.x)], 1);
    g_p2s[PAD + s2] = p2;
    float4 w = g_warp[i];
    int sw = atomicAdd(&g_bins[2 * NB + bucketf(w.x)], 1);
    g_ws[PAD + sw] = w;
    g_idxw[sw] = i;
}

// Pass 1: branchless distance-only sorted top-K (ascending; d[K-1] = kth).
// dm = |p|^2 - 2<q,p>; true dist = dm + q.w. Records scanned window [lo,hi).
template <int K>
__device__ __forceinline__ void pass1(const float4* __restrict__ C, float4 q,
                                      int mid, int n, int dir, float4* sp,
                                      float (&d)[K], int& lo, int& hi) {
    #pragma unroll
    for (int t = 0; t < K; t++) d[t] = 3.4e38f;
    if (dir == 0) {
        int j = mid - TPB;                 // mid >= PAD = TPB
        for (;;) {
            __syncthreads();
            sp[threadIdx.x] = C[j + threadIdx.x];
            __syncthreads();
            #pragma unroll 4
            for (int t = 0; t < TPB; t++) {
                float4 p = sp[t];
                float dot = fmaf(q.x, p.x, fmaf(q.y, p.y, q.z * p.z));
                float dm  = fmaf(-2.f, dot, p.w);
                d[K - 1] = fminf(d[K - 1], dm);
                #pragma unroll
                for (int s = K - 1; s > 0; --s) {
                    float a = fminf(d[s - 1], d[s]);
                    float b = fmaxf(d[s - 1], d[s]);
                    d[s - 1] = a; d[s] = b;
                }
            }
            j -= TPB;
            if (j < 0) break;
            float fx = C[j + TPB - 1].x;
            float dxm = q.x - fx - BW;
            bool sat = (dxm > 0.f) && (dxm * dxm > d[K - 1] + q.w);
            if (__syncthreads_and(sat)) break;
        }
        lo = j + TPB; hi = mid;
    } else {
        int j = mid;
        const int jend = PAD + n;
        while (j < jend) {
            __syncthreads();
            sp[threadIdx.x] = C[j + threadIdx.x];
            __syncthreads();
            #pragma unroll 4
            for (int t = 0; t < TPB; t++) {
                float4 p = sp[t];
                float dot = fmaf(q.x, p.x, fmaf(q.y, p.y, q.z * p.z));
                float dm  = fmaf(-2.f, dot, p.w);
                d[K - 1] = fminf(d[K - 1], dm);
                #pragma unroll
                for (int s = K - 1; s > 0; --s) {
                    float a = fminf(d[s - 1], d[s]);
                    float b = fmaxf(d[s - 1], d[s]);
                    d[s - 1] = a; d[s] = b;
                }
            }
            j += TPB;
            if (j >= jend) break;
            float fx = C[j].x;
            float dxm = fx - q.x - BW;
            bool sat = (dxm > 0.f) && (dxm * dxm > d[K - 1] + q.w);
            if (__syncthreads_and(sat)) break;
        }
        lo = mid; hi = j;
    }
}

// Pass 2: rescan window near-to-far; member iff dm <= kth (same FMA sequence
// as pass 1 -> deterministic). Writes (true dist, padded sorted id) into the
// per-side scratch; sentinel-fills unused slots.
template <int K>
__device__ __forceinline__ void pass2(const float4* __restrict__ C, float4 q,
                                      int lo, int hi, int dir, float4* sp,
                                      float kth, int b) {
    int cnt = 0;
    if (dir == 0) {
        for (int jj = hi - TPB; jj >= lo; jj -= TPB) {   // near-to-far
            __syncthreads();
            sp[threadIdx.x] = C[jj + threadIdx.x];
            __syncthreads();
            for (int t = TPB - 1; t >= 0; --t) {
                float4 p = sp[t];
                float dot = fmaf(q.x, p.x, fmaf(q.y, p.y, q.z * p.z));
                float dm  = fmaf(-2.f, dot, p.w);
                if (dm <= kth && cnt < K) {
                    g_pd[b + cnt] = dm + q.w;
                    g_pi[b + cnt] = jj + t;
                    cnt++;
                }
            }
        }
    } else {
        for (int jj = lo; jj < hi; jj += TPB) {          // near-to-far
            __syncthreads();
            sp[threadIdx.x] = C[jj + threadIdx.x];
            __syncthreads();
            for (int t = 0; t < TPB; t++) {
                float4 p = sp[t];
                float dot = fmaf(q.x, p.x, fmaf(q.y, p.y, q.z * p.z));
                float dm  = fmaf(-2.f, dot, p.w);
                if (dm <= kth && cnt < K) {
                    g_pd[b + cnt] = dm + q.w;
                    g_pi[b + cnt] = jj + t;
                    cnt++;
                }
            }
        }
    }
    for (int t = cnt; t < K; t++) { g_pd[b + t] = 3.4e38f; g_pi[b + t] = PAD; }
}

// min-only variant (reverse chamfer)
__device__ __forceinline__ float wmin(const float4* __restrict__ C, float4 q,
                                      int mid, int n, int dir, float4* sp) {
    float m = 3.4e38f;
    if (dir == 0) {
        int j = mid - TPB;
        for (;;) {
            __syncthreads();
            sp[threadIdx.x] = C[j + threadIdx.x];
            __syncthreads();
            #pragma unroll 8
            for (int t = TPB - 1; t >= 0; --t) {
                float4 p = sp[t];
                float dot = fmaf(q.x, p.x, fmaf(q.y, p.y, q.z * p.z));
                m = fminf(m, fmaf(-2.f, dot, p.w));
            }
            j -= TPB;
            if (j < 0) break;
            float fx = C[j + TPB - 1].x;
            float dxm = q.x - fx - BW;
            bool sat = (dxm > 0.f) && (dxm * dxm > m + q.w);
            if (__syncthreads_and(sat)) break;
        }
    } else {
        int j = mid;
        const int jend = PAD + n;
        while (j < jend) {
            __syncthreads();
            sp[threadIdx.x] = C[j + threadIdx.x];
            __syncthreads();
            #pragma unroll 8
            for (int t = 0; t < TPB; ++t) {
                float4 p = sp[t];
                float dot = fmaf(q.x, p.x, fmaf(q.y, p.y, q.z * p.z));
                m = fminf(m, fmaf(-2.f, dot, p.w));
            }
            j += TPB;
            if (j >= jend) break;
            float fx = C[j].x;
            float dxm = fx - q.x - BW;
            bool sat = (dxm > 0.f) && (dxm * dxm > m + q.w);
            if (__syncthreads_and(sat)) break;
        }
    }
    return m;
}

// grid = (n/TPB, 2, 4): y = side, z = slice.
__global__ void __launch_bounds__(TPB) pairs_kernel(int n, const int* __restrict__ kptr) {
    __shared__ float4 sp[TPB];
    const int slice = blockIdx.z;
    const int dir = blockIdx.y;
    const int qbase = blockIdx.x * TPB;
    const int i = qbase + threadIdx.x;

    const float4* __restrict__ Q;
    const float4* __restrict__ C;
    int hc;
    if      (slice == 0) { Q = g_p2s; C = g_p2s; hc = 1; }
    else if (slice == 1) { Q = g_p1s; C = g_p1s; hc = 0; }
    else if (slice == 2) { Q = g_ws;  C = g_p2s; hc = 1; }
    else                 { Q = g_p2s; C = g_ws;  hc = 2; }

    float4 q = Q[PAD + i];
    float xmed = Q[PAD + qbase + TPB / 2].x;
    int mid = PAD + g_bins[hc * NB + bucketf(xmed)];

    if (slice == 0 || slice == 1) {
        float d[KNN]; int lo, hi;
        pass1<KNN>(C, q, mid, n, dir, sp, d, lo, hi);
        int b = ((slice * MAXN + i) * 2 + dir) * KNN;
        pass2<KNN>(C, q, lo, hi, dir, sp, d[KNN - 1], b);
    } else if (slice == 2) {
        float d[KNN5]; int lo, hi;
        pass1<KNN5>(C, q, mid, n, dir, sp, d, lo, hi);
        int b = ((2 * MAXN + i) * 2 + dir) * KNN;
        pass2<KNN5>(C, q, lo, hi, dir, sp, d[KNN5 - 1], b);
    } else {
        float m = wmin(C, q, mid, n, dir, sp);
        g_pmin[i * 2 + dir] = m + q.w;
    }
}

// Stable 2-chunk merge (true distances, strict '<'); ids are padded sorted
// positions; sentinels (3.4e38, PAD) never win. Ties measure-zero.
template <int K>
__device__ __forceinline__ void merge_topk(int r, int i, float (&d)[K], int (&id)[K]) {
    #pragma unroll
    for (int t = 0; t < K; t++) { d[t] = 3.4e38f; id[t] = PAD; }
    int base = (r * MAXN + i) * 2 * KNN;
    #pragma unroll
    for (int c = 0; c < 2; c++) {
        #pragma unroll
        for (int t = 0; t < K; t++) {
            float dist = g_pd[base + c * KNN + t];
            int j = g_pi[base + c * KNN + t];
            if (dist < d[K - 1]) {
                d[K - 1] = dist; id[K - 1] = j;
                #pragma unroll
                for (int s = K - 1; s > 0; --s) {
                    if (d[s] < d[s - 1]) {
                        float td = d[s]; d[s] = d[s - 1]; d[s - 1] = td;
                        int   ti = id[s]; id[s] = id[s - 1]; id[s - 1] = ti;
                    }
                }
            }
        }
    }
}

// grid.y: 0 = c2 curvature, 1 = moved curvature + smoothness, 2 = reverse chamfer
__global__ void consumeA_kernel(int n, const int* __restrict__ kptr) {
    int i = blockIdx.x * blockDim.x + threadIdx.x;
    int task = blockIdx.y;
    if (task == 0) {
        if (i >= n) return;
        float d[KNN]; int id[KNN];
        merge_topk<KNN>(0, i, d, id);
        float4 qq = g_p2s[PAD + i];
        float sx = 0.f, sy = 0.f, sz = 0.f;
        #pragma unroll
        for (int t = 0; t < KNN; t++) {
            float4 p = g_p2s[id[t]];
            sx += p.x; sy += p.y; sz += p.z;
        }
        g_c2s[PAD + i] = make_float4((sx - 10.f * qq.x) / 9.f,
                                     (sy - 10.f * qq.y) / 9.f,
                                     (sz - 10.f * qq.z) / 9.f, 0.f);
    } else if (task == 1) {
        double sm_d = 0.0;
        if (i < n) {
            float d[KNN]; int id[KNN];
            merge_topk<KNN>(1, i, d, id);
            float4 w = g_warp1s[PAD + i];
            float sx = 0.f, sy = 0.f, sz = 0.f;
            #pragma unroll
            for (int t = 0; t < KNN; t++) {
                float4 p = g_warp1s[id[t]];
                sx += p.x; sy += p.y; sz += p.z;
            }
            g_moved[g_idx1[i]] = make_float4((sx - 10.f * w.x) / 9.f,
                                             (sy - 10.f * w.y) / 9.f,
                                             (sz - 10.f * w.z) / 9.f, 0.f);
            int k = *kptr;
            float4 f = g_flow1s[PAD + i];
            float sm = 0.f;
            #pragma unroll
            for (int t = 0; t < KNN; t++) {
                if (t < k) {
                    float4 gfl = g_flow1s[id[t]];
                    float dx = gfl.x - f.x, dy = gfl.y - f.y, dz = gfl.z - f.z;
                    float sq = dx * dx + dy * dy + dz * dz;
                    sm += sqrtf(sq);   // sq==0 (self) -> 0, matches safe-norm
                }
            }
            sm_d = (double)(sm / 8.f);
        }
        double v = warp_red(sm_d);
        if ((threadIdx.x & 31) == 0) atomicAdd(&g_acc[2], v);
    } else {
        double v = 0.0;
        if (i < n) v = (double)fminf(g_pmin[i * 2], g_pmin[i * 2 + 1]);
        double s = warp_red(v);
        if ((threadIdx.x & 31) == 0) atomicAdd(&g_acc[1], s);
    }
}

// warp->pc2 top-5 merge -> chamfer fwd + interp-curvature; last block finalizes.
__global__ void cross_consume_kernel(int n, float* __restrict__ out) {
    int i = blockIdx.x * blockDim.x + threadIdx.x;
    double d1 = 0.0, cv = 0.0;
    if (i < n) {
        float d[KNN5]; int id[KNN5];
        merge_topk<KNN5>(2, i, d, id);
        d1 = (double)d[0];
        float w[KNN5]; float wsum = 0.f;
        #pragma unroll
        for (int t = 0; t < KNN5; t++) { w[t] = 1.f / (d[t] + 1e-8f); wsum += w[t]; }
        float ix = 0.f, iy = 0.f, iz = 0.f;
        #pragma unroll
        for (int t = 0; t < KNN5; t++) {
            float wn = w[t] / wsum;
            float4 c = g_c2s[id[t]];
            ix = fmaf(wn, c.x, ix);
            iy = fmaf(wn, c.y, iy);
            iz = fmaf(wn, c.z, iz);
        }
        float4 m = g_moved[g_idxw[i]];
        float ex = ix - m.x, ey = iy - m.y, ez = iz - m.z;
        cv = (double)(ex * ex + ey * ey + ez * ez);
    }
    double v0 = warp_red(d1);
    double v1 = warp_red(cv);
    if ((threadIdx.x & 31) == 0) {
        atomicAdd(&g_acc[0], v0);
        atomicAdd(&g_acc[3], v1);
    }
    __threadfence();
    __syncthreads();
    if (threadIdx.x == 0) {
        int t = atomicAdd(&g_ticket, 1);
        if (t == (int)gridDim.x - 1) {
            __threadfence();
            double a0 = *((volatile double*)&g_acc[0]);
            double a1 = *((volatile double*)&g_acc[1]);
            double a2 = *((volatile double*)&g_acc[2]);
            double a3 = *((volatile double*)&g_acc[3]);
            out[0] = (float)(0.02 * (a0 + a1) + 0.006 * a3 + 0.01 * a2);
        }
    }
}

extern "C" void kernel_launch(void* const* d_in, const int* in_sizes, int n_in,
                              void* d_out, int out_size) {
    const float* pred   = (const float*)d_in[0];  // registration_pred (1,N,3)
    const float* gt     = (const float*)d_in[1];  // registration_gt   (1,N,3)
    const float* coords = (const float*)d_in[2];  // coords            (N,3)
    const int*   kptr   = (const int*)d_in[3];    // smoothness_k

    int n = in_sizes[2] / 3;   // 8192
    int cb = (n + 255) / 256;

    zero_kernel<<<3, 1024>>>();
    prep_kernel<<<cb, 256>>>(pred, gt, coords, n);
    scan_kernel<<<1, NB>>>();
    scatter_kernel<<<cb, 256>>>(n);
    pairs_kernel<<<dim3(n / TPB, 2, 4), TPB>>>(n, kptr);
    consumeA_kernel<<<dim3(cb, 3), 256>>>(n, kptr);
    cross_consume_kernel<<<cb, 256>>>(n, (float*)d_out);
}

// round 16
// speedup vs baseline: 1.8389x; 1.8389x over previous
#include <cuda_runtime.h>
#include <cuda_bf16.h>

// PointPWC loss, B=1, N=8192.
// total = 0.02*chamfer + 0.006*curv + 0.01*smooth
//
// R15 = R11 (passing, 332us) + kth SEEDING. Only change to the scan: kth is
// initialized from a precomputed per-query upper bound (max distance over ~10
// x-sorted neighbor candidates, bumped by ~1e-6 relative so the seed-defining
// candidate itself passes the strict '<' guard). true_kth <= seed since the
// seed is the max over >=K real candidates. Insert-chain events (the dominant
// cost in every prior round) collapse to ~true members only; the prune vote
// also converges immediately. Merge/consume/tie-order identical to R11.

#define MAXN  8192
#define KNN   10
#define KNN5  5
#define TPB   256
#define PAD   256
#define PADN  (MAXN + 2 * PAD)
#define NB    1024
#define XMIN  (-8.0f)
#define BSCALE 64.0f           // NB / 16
#define BW    0.015625f        // 16 / NB

__device__ float4 g_pc1[MAXN], g_pc2[MAXN], g_warp[MAXN], g_flow[MAXN];
__device__ float4 g_p1s[PADN], g_p2s[PADN], g_ws[PADN];     // sorted + pads
__device__ float4 g_flow1s[PADN], g_warp1s[PADN];           // pc1-sorted order
__device__ int    g_idx1[MAXN];   // pc1-sorted -> orig
__device__ int    g_idxw[MAXN];   // warp-sorted -> orig
__device__ float4 g_c2s[PADN];    // curvature of pc2, padded sorted pos
__device__ float4 g_moved[MAXN];  // moved curvature, orig order
// i-major partials: ((r*MAXN + i)*2 + dir)*KNN + t
__device__ float  g_pd[3 * MAXN * 2 * KNN];
__device__ int    g_pi[3 * MAXN * 2 * KNN];
__device__ float  g_pmin[MAXN * 2];
__device__ float  g_seed[3 * MAXN];   // dm-space kth upper bounds
__device__ int    g_bins[3 * NB];
__device__ double g_acc[4];  // 0: chamfer fwd, 1: chamfer bwd, 2: smooth, 3: curv

__device__ __forceinline__ int bucketf(float x) {
    int b = (int)((x - XMIN) * BSCALE);
    return min(max(b, 0), NB - 1);
}

__device__ __forceinline__ double warp_red(double v) {
    #pragma unroll
    for (int o = 16; o > 0; o >>= 1)
        v += __shfl_down_sync(0xffffffffu, v, o);
    return v;
}

__global__ void zero_kernel() {
    int gid = blockIdx.x * blockDim.x + threadIdx.x;
    if (gid < 3 * NB) g_bins[gid] = 0;
    if (gid < 4) g_acc[gid] = 0.0;
    if (gid < PAD) {
        float4 lp = make_float4(-1e18f, 0.f, 0.f, 3.4e38f);
        float4 rp = make_float4( 1e18f, 0.f, 0.f, 3.4e38f);
        g_p1s[gid] = lp; g_p1s[PAD + MAXN + gid] = rp;
        g_p2s[gid] = lp; g_p2s[PAD + MAXN + gid] = rp;
        g_ws[gid]  = lp; g_ws[PAD + MAXN + gid]  = rp;
    }
}

__global__ void prep_kernel(const float* __restrict__ pred,
                            const float* __restrict__ gt,
                            const float* __restrict__ coords, int n) {
    int i = blockIdx.x * blockDim.x + threadIdx.x;
    if (i >= n) return;
    float cx = coords[3 * i + 0], cy = coords[3 * i + 1], cz = coords[3 * i + 2];
    float gx = gt[3 * i + 0],     gy = gt[3 * i + 1],     gz = gt[3 * i + 2];
    float fx = pred[3 * i + 0],   fy = pred[3 * i + 1],   fz = pred[3 * i + 2];
    float p2x = cx + gx, p2y = cy + gy, p2z = cz + gz;
    float wx  = cx + fx, wy  = cy + fy, wz  = cz + fz;
    g_pc1[i]  = make_float4(cx, cy, cz, cx * cx + cy * cy + cz * cz);
    g_pc2[i]  = make_float4(p2x, p2y, p2z, p2x * p2x + p2y * p2y + p2z * p2z);
    g_warp[i] = make_float4(wx, wy, wz, wx * wx + wy * wy + wz * wz);
    g_flow[i] = make_float4(fx, fy, fz, 0.f);
    atomicAdd(&g_bins[bucketf(cx)], 1);
    atomicAdd(&g_bins[NB + bucketf(p2x)], 1);
    atomicAdd(&g_bins[2 * NB + bucketf(wx)], 1);
}

__global__ void scan_kernel() {
    __shared__ int s[NB];
    int t = threadIdx.x;
    for (int h = 0; h < 3; h++) {
        int orig = g_bins[h * NB + t];
        s[t] = orig;
        __syncthreads();
        for (int o = 1; o < NB; o <<= 1) {
            int v = (t >= o) ? s[t - o] : 0;
            __syncthreads();
            s[t] += v;
            __syncthreads();
        }
        g_bins[h * NB + t] = s[t] - orig;  // exclusive start
        __syncthreads();
    }
}

// after this kernel g_bins holds bucket END offsets
__global__ void scatter_kernel(int n) {
    int i = blockIdx.x * blockDim.x + threadIdx.x;
    if (i >= n) return;
    float4 p1 = g_pc1[i];
    int s1 = atomicAdd(&g_bins[bucketf(p1.x)], 1);
    g_p1s[PAD + s1] = p1;
    g_flow1s[PAD + s1] = g_flow[i];
    g_warp1s[PAD + s1] = g_warp[i];
    g_idx1[s1] = i;
    float4 p2 = g_pc2[i];
    int s2 = atomicAdd(&g_bins[NB + bucketf(p2.x)], 1);
    g_p2s[PAD + s2] = p2;
    float4 w = g_warp[i];
    int sw = atomicAdd(&g_bins[2 * NB + bucketf(w.x)], 1);
    g_ws[PAD + sw] = w;
    g_idxw[sw] = i;
}

// kth upper-bound seeds (dm-space). r=0: p2s self (10 neighbors, i+-1..5);
// r=1: p1s self; r=2: ws->p2s (6 neighbors around bucket position, >=5 => valid
// bound for K=5). Relative bump so the seed-defining candidate passes '<'.
__global__ void seed_kernel(int n) {
    int i = blockIdx.x * blockDim.x + threadIdx.x;
    int r = blockIdx.y;
    if (i >= n) return;
    float4 q;
    float mx = -3.4e38f;
    if (r < 2) {
        const float4* __restrict__ C = (r == 0) ? g_p2s : g_p1s;
        q = C[PAD + i];
        #pragma unroll
        for (int t = -5; t <= 5; t++) {
            if (t == 0) continue;
            float4 p = C[PAD + i + t];
            float dot = fmaf(q.x, p.x, fmaf(q.y, p.y, q.z * p.z));
            float dm  = fmaf(-2.f, dot, p.w);
            mx = fmaxf(mx, dm);
        }
    } else {
        q = g_ws[PAD + i];
        int pos = g_bins[NB + bucketf(q.x)];   // bucket end in p2s order
        #pragma unroll
        for (int t = -3; t <= 2; t++) {
            float4 p = g_p2s[PAD + pos + t];
            float dot = fmaf(q.x, p.x, fmaf(q.y, p.y, q.z * p.z));
            float dm  = fmaf(-2.f, dot, p.w);
            mx = fmaxf(mx, dm);
        }
    }
    g_seed[r * MAXN + i] = mx + fabsf(mx) * 1e-6f + 1e-30f;
}

template <int K>
__device__ __forceinline__ void insert_sorted(float dm, int j,
                                              float (&d)[K], int (&id)[K],
                                              float& kth, float seed) {
    d[K - 1] = dm; id[K - 1] = j;
    #pragma unroll
    for (int s = K - 1; s > 0; --s) {
        if (d[s] < d[s - 1]) {
            float td = d[s]; d[s] = d[s - 1]; d[s - 1] = td;
            int   ti = id[s]; id[s] = id[s - 1]; id[s - 1] = ti;
        }
    }
    kth = fminf(d[K - 1], seed);
}

// Windowed outward scan (one side), seeded kth. dm = |p|^2 - 2<q,p>;
// true = dm + q.w. Block-uniform vote stops the walk when every lane's
// slack-adjusted x-gap to the frontier exceeds kth_true (seed is an upper
// bound on true kth, so pruning stays safe). Pads force the vote at bounds.
template <int K>
__device__ __forceinline__ void wscan(const float4* __restrict__ C, float4 q,
                                      int mid, int n, int dir, float4* sp,
                                      float seed, float (&d)[K], int (&id)[K]) {
    #pragma unroll
    for (int t = 0; t < K; t++) { d[t] = 3.4e38f; id[t] = PAD; }
    float kth = seed;
    if (dir == 0) {
        int j = mid - TPB;            // mid >= PAD = TPB, so j >= 0
        for (;;) {
            __syncthreads();
            sp[threadIdx.x] = C[j + threadIdx.x];
            __syncthreads();
            #pragma unroll 8
            for (int t = TPB - 1; t >= 0; --t) {   // near-to-far
                float4 p = sp[t];
                float dot = fmaf(q.x, p.x, fmaf(q.y, p.y, q.z * p.z));
                float dm  = fmaf(-2.f, dot, p.w);
                if (dm < kth) insert_sorted<K>(dm, j + t, d, id, kth, seed);
            }
            j -= TPB;
            if (j < 0) break;
            float fx = C[j + TPB - 1].x;
            float dxm = q.x - fx - BW;
            bool sat = (dxm > 0.f) && (dxm * dxm > kth + q.w);
            if (__syncthreads_and(sat)) break;
        }
    } else {
        int j = mid;
        const int jend = PAD + n;
        while (j < jend) {
            __syncthreads();
            sp[threadIdx.x] = C[j + threadIdx.x];
            __syncthreads();
            #pragma unroll 8
            for (int t = 0; t < TPB; ++t) {        // near-to-far
                float4 p = sp[t];
                float dot = fmaf(q.x, p.x, fmaf(q.y, p.y, q.z * p.z));
                float dm  = fmaf(-2.f, dot, p.w);
                if (dm < kth) insert_sorted<K>(dm, j + t, d, id, kth, seed);
            }
            j += TPB;
            if (j >= jend) break;
            float fx = C[j].x;
            float dxm = fx - q.x - BW;
            bool sat = (dxm > 0.f) && (dxm * dxm > kth + q.w);
            if (__syncthreads_and(sat)) break;
        }
    }
}

// min-only variant (reverse chamfer) — unchanged from R11
__device__ __forceinline__ float wmin(const float4* __restrict__ C, float4 q,
                                      int mid, int n, int dir, float4* sp) {
    float m = 3.4e38f;
    if (dir == 0) {
        int j = mid - TPB;
        for (;;) {
            __syncthreads();
            sp[threadIdx.x] = C[j + threadIdx.x];
            __syncthreads();
            #pragma unroll 8
            for (int t = TPB - 1; t >= 0; --t) {
                float4 p = sp[t];
                float dot = fmaf(q.x, p.x, fmaf(q.y, p.y, q.z * p.z));
                m = fminf(m, fmaf(-2.f, dot, p.w));
            }
            j -= TPB;
            if (j < 0) break;
            float fx = C[j + TPB - 1].x;
            float dxm = q.x - fx - BW;
            bool sat = (dxm > 0.f) && (dxm * dxm > m + q.w);
            if (__syncthreads_and(sat)) break;
        }
    } else {
        int j = mid;
        const int jend = PAD + n;
        while (j < jend) {
            __syncthreads();
            sp[threadIdx.x] = C[j + threadIdx.x];
            __syncthreads();
            #pragma unroll 8
            for (int t = 0; t < TPB; ++t) {
                float4 p = sp[t];
                float dot = fmaf(q.x, p.x, fmaf(q.y, p.y, q.z * p.z));
                m = fminf(m, fmaf(-2.f, dot, p.w));
            }
            j += TPB;
            if (j >= jend) break;
            float fx = C[j].x;
            float dxm = fx - q.x - BW;
            bool sat = (dxm > 0.f) && (dxm * dxm > m + q.w);
            if (__syncthreads_and(sat)) break;
        }
    }
    return m;
}

// grid = (n/TPB, 2, 4): y = side, z = slice.
__global__ void __launch_bounds__(TPB) pairs_kernel(int n, const int* __restrict__ kptr) {
    __shared__ float4 sp[TPB];
    const int slice = blockIdx.z;
    const int dir = blockIdx.y;
    const int qbase = blockIdx.x * TPB;
    const int i = qbase + threadIdx.x;

    const float4* __restrict__ Q;
    const float4* __restrict__ C;
    int hc;
    if      (slice == 0) { Q = g_p2s; C = g_p2s; hc = 1; }
    else if (slice == 1) { Q = g_p1s; C = g_p1s; hc = 0; }
    else if (slice == 2) { Q = g_ws;  C = g_p2s; hc = 1; }
    else                 { Q = g_p2s; C = g_ws;  hc = 2; }

    float4 q = Q[PAD + i];
    float xmed = Q[PAD + qbase + TPB / 2].x;
    int mid = PAD + g_bins[hc * NB + bucketf(xmed)];

    if (slice == 0 || slice == 1) {
        float seed = g_seed[slice * MAXN + i];
        float d[KNN]; int id[KNN];
        wscan<KNN>(C, q, mid, n, dir, sp, seed, d, id);
        int b = ((slice * MAXN + i) * 2 + dir) * KNN;
        #pragma unroll
        for (int t = 0; t < KNN; t++) { g_pd[b + t] = d[t] + q.w; g_pi[b + t] = id[t]; }
    } else if (slice == 2) {
        float seed = g_seed[2 * MAXN + i];
        float d[KNN5]; int id[KNN5];
        wscan<KNN5>(C, q, mid, n, dir, sp, seed, d, id);
        int b = ((2 * MAXN + i) * 2 + dir) * KNN;
        #pragma unroll
        for (int t = 0; t < KNN5; t++) { g_pd[b + t] = d[t] + q.w; g_pi[b + t] = id[t]; }
    } else {
        float m = wmin(C, q, mid, n, dir, sp);
        g_pmin[i * 2 + dir] = m + q.w;
    }
}

// Stable 2-chunk merge (true distances, strict '<'); sentinels never win.
template <int K>
__device__ __forceinline__ void merge_topk(int r, int i, float (&d)[K], int (&id)[K]) {
    #pragma unroll
    for (int t = 0; t < K; t++) { d[t] = 3.4e38f; id[t] = PAD; }
    int base = (r * MAXN + i) * 2 * KNN;
    #pragma unroll
    for (int c = 0; c < 2; c++) {
        #pragma unroll
        for (int t = 0; t < K; t++) {
            float dist = g_pd[base + c * KNN + t];
            int j = g_pi[base + c * KNN + t];
            if (dist < d[K - 1]) {
                d[K - 1] = dist; id[K - 1] = j;
                #pragma unroll
                for (int s = K - 1; s > 0; --s) {
                    if (d[s] < d[s - 1]) {
                        float td = d[s]; d[s] = d[s - 1]; d[s - 1] = td;
                        int   ti = id[s]; id[s] = id[s - 1]; id[s - 1] = ti;
                    }
                }
            }
        }
    }
}

// grid.y: 0 = c2 curvature, 1 = moved curvature + smoothness, 2 = reverse chamfer
__global__ void consumeA_kernel(int n, const int* __restrict__ kptr) {
    int i = blockIdx.x * blockDim.x + threadIdx.x;
    int task = blockIdx.y;
    if (task == 0) {
        if (i >= n) return;
        float d[KNN]; int id[KNN];
        merge_topk<KNN>(0, i, d, id);
        float4 qq = g_p2s[PAD + i];
        float sx = 0.f, sy = 0.f, sz = 0.f;
        #pragma unroll
        for (int t = 0; t < KNN; t++) {
            float4 p = g_p2s[id[t]];
            sx += p.x; sy += p.y; sz += p.z;
        }
        g_c2s[PAD + i] = make_float4((sx - 10.f * qq.x) / 9.f,
                                     (sy - 10.f * qq.y) / 9.f,
                                     (sz - 10.f * qq.z) / 9.f, 0.f);
    } else if (task == 1) {
        double sm_d = 0.0;
        if (i < n) {
            float d[KNN]; int id[KNN];
            merge_topk<KNN>(1, i, d, id);
            float4 w = g_warp1s[PAD + i];
            float sx = 0.f, sy = 0.f, sz = 0.f;
            #pragma unroll
            for (int t = 0; t < KNN; t++) {
                float4 p = g_warp1s[id[t]];
                sx += p.x; sy += p.y; sz += p.z;
            }
            g_moved[g_idx1[i]] = make_float4((sx - 10.f * w.x) / 9.f,
                                             (sy - 10.f * w.y) / 9.f,
                                             (sz - 10.f * w.z) / 9.f, 0.f);
            int k = *kptr;
            float4 f = g_flow1s[PAD + i];
            float sm = 0.f;
            #pragma unroll
            for (int t = 0; t < KNN; t++) {
                if (t < k) {
                    float4 gfl = g_flow1s[id[t]];
                    float dx = gfl.x - f.x, dy = gfl.y - f.y, dz = gfl.z - f.z;
                    float sq = dx * dx + dy * dy + dz * dz;
                    sm += sqrtf(sq);   // sq==0 (self) -> 0, matches safe-norm
                }
            }
            sm_d = (double)(sm / 8.f);
        }
        double v = warp_red(sm_d);
        if ((threadIdx.x & 31) == 0) atomicAdd(&g_acc[2], v);
    } else {
        double v = 0.0;
        if (i < n) v = (double)fminf(g_pmin[i * 2], g_pmin[i * 2 + 1]);
        double s = warp_red(v);
        if ((threadIdx.x & 31) == 0) atomicAdd(&g_acc[1], s);
    }
}

// warp->pc2 top-5 merge -> chamfer fwd + interpolated-curvature loss
__global__ void cross_consume_kernel(int n) {
    int i = blockIdx.x * blockDim.x + threadIdx.x;
    double d1 = 0.0, cv = 0.0;
    if (i < n) {
        float d[KNN5]; int id[KNN5];
        merge_topk<KNN5>(2, i, d, id);
        d1 = (double)d[0];
        float w[KNN5]; float wsum = 0.f;
        #pragma unroll
        for (int t = 0; t < KNN5; t++) { w[t] = 1.f / (d[t] + 1e-8f); wsum += w[t]; }
        float ix = 0.f, iy = 0.f, iz = 0.f;
        #pragma unroll
        for (int t = 0; t < KNN5; t++) {
            float wn = w[t] / wsum;
            float4 c = g_c2s[id[t]];
            ix = fmaf(wn, c.x, ix);
            iy = fmaf(wn, c.y, iy);
            iz = fmaf(wn, c.z, iz);
        }
        float4 m = g_moved[g_idxw[i]];
        float ex = ix - m.x, ey = iy - m.y, ez = iz - m.z;
        cv = (double)(ex * ex + ey * ey + ez * ez);
    }
    double v0 = warp_red(d1);
    double v1 = warp_red(cv);
    if ((threadIdx.x & 31) == 0) {
        atomicAdd(&g_acc[0], v0);
        atomicAdd(&g_acc[3], v1);
    }
}

__global__ void finalize_kernel(float* __restrict__ out) {
    if (threadIdx.x == 0) {
        double chamfer = g_acc[0] + g_acc[1];
        double total = 0.02 * chamfer      // F_CHAMFER * ALPHA0
                     + 0.006 * g_acc[3]    // F_CURVATURE * ALPHA0
                     + 0.01  * g_acc[2];   // F_SMOOTH * ALPHA0
        out[0] = (float)total;
    }
}

extern "C" void kernel_launch(void* const* d_in, const int* in_sizes, int n_in,
                              void* d_out, int out_size) {
    const float* pred   = (const float*)d_in[0];  // registration_pred (1,N,3)
    const float* gt     = (const float*)d_in[1];  // registration_gt   (1,N,3)
    const float* coords = (const float*)d_in[2];  // coords            (N,3)
    const int*   kptr   = (const int*)d_in[3];    // smoothness_k

    int n = in_sizes[2] / 3;   // 8192
    int cb = (n + 255) / 256;

    zero_kernel<<<3, 1024>>>();
    prep_kernel<<<cb, 256>>>(pred, gt, coords, n);
    scan_kernel<<<1, NB>>>();
    scatter_kernel<<<cb, 256>>>(n);
    seed_kernel<<<dim3(cb, 3), 256>>>(n);
    pairs_kernel<<<dim3(n / TPB, 2, 4), TPB>>>(n, kptr);
    consumeA_kernel<<<dim3(cb, 3), 256>>>(n, kptr);
    cross_consume_kernel<<<cb, 256>>>(n);
    finalize_kernel<<<1, 32>>>((float*)d_out);
}

// round 17
// speedup vs baseline: 1.8829x; 1.0239x over previous
#include <cuda_runtime.h>
#include <cuda_bf16.h>

// PointPWC loss, B=1, N=8192.
// total = 0.02*chamfer + 0.006*curv + 0.01*smooth
//
// R16 = R15 (passing, 287us) + incremental bundle:
//  - pairs TPB 128 (512 blocks): finer vote granularity + better SM balance
//  - per-warp early-skip: a warp whose lanes all pass the frontier bound
//    latches done and skips the inner loop (still loads tiles / hits barriers)
//  - seed computation inlined into pairs (seed_kernel removed)
//  - finalize folded into cross_consume via ticket (R13 mechanism)
//  - scan_kernel parallelized across 3 blocks (one per histogram)
//  Selection math identical to R15 -> same rel_err expected.

#define MAXN  8192
#define KNN   10
#define KNN5  5
#define TPB   256      // aux kernels
#define PTPB  128      // pairs kernel
#define PAD   256
#define PADN  (MAXN + 2 * PAD)
#define NB    1024
#define XMIN  (-8.0f)
#define BSCALE 64.0f           // NB / 16
#define BW    0.015625f        // 16 / NB

__device__ float4 g_pc1[MAXN], g_pc2[MAXN], g_warp[MAXN], g_flow[MAXN];
__device__ float4 g_p1s[PADN], g_p2s[PADN], g_ws[PADN];     // sorted + pads
__device__ float4 g_flow1s[PADN], g_warp1s[PADN];           // pc1-sorted order
__device__ int    g_idx1[MAXN];   // pc1-sorted -> orig
__device__ int    g_idxw[MAXN];   // warp-sorted -> orig
__device__ float4 g_c2s[PADN];    // curvature of pc2, padded sorted pos
__device__ float4 g_moved[MAXN];  // moved curvature, orig order
// i-major partials: ((r*MAXN + i)*2 + dir)*KNN + t
__device__ float  g_pd[3 * MAXN * 2 * KNN];
__device__ int    g_pi[3 * MAXN * 2 * KNN];
__device__ float  g_pmin[MAXN * 2];
__device__ int    g_bins[3 * NB];
__device__ int    g_ticket;
__device__ double g_acc[4];  // 0: chamfer fwd, 1: chamfer bwd, 2: smooth, 3: curv

__device__ __forceinline__ int bucketf(float x) {
    int b = (int)((x - XMIN) * BSCALE);
    return min(max(b, 0), NB - 1);
}

__device__ __forceinline__ double warp_red(double v) {
    #pragma unroll
    for (int o = 16; o > 0; o >>= 1)
        v += __shfl_down_sync(0xffffffffu, v, o);
    return v;
}

__global__ void zero_kernel() {
    int gid = blockIdx.x * blockDim.x + threadIdx.x;
    if (gid < 3 * NB) g_bins[gid] = 0;
    if (gid < 4) g_acc[gid] = 0.0;
    if (gid == 4) g_ticket = 0;
    if (gid < PAD) {
        float4 lp = make_float4(-1e18f, 0.f, 0.f, 3.4e38f);
        float4 rp = make_float4( 1e18f, 0.f, 0.f, 3.4e38f);
        g_p1s[gid] = lp; g_p1s[PAD + MAXN + gid] = rp;
        g_p2s[gid] = lp; g_p2s[PAD + MAXN + gid] = rp;
        g_ws[gid]  = lp; g_ws[PAD + MAXN + gid]  = rp;
    }
}

__global__ void prep_kernel(const float* __restrict__ pred,
                            const float* __restrict__ gt,
                            const float* __restrict__ coords, int n) {
    int i = blockIdx.x * blockDim.x + threadIdx.x;
    if (i >= n) return;
    float cx = coords[3 * i + 0], cy = coords[3 * i + 1], cz = coords[3 * i + 2];
    float gx = gt[3 * i + 0],     gy = gt[3 * i + 1],     gz = gt[3 * i + 2];
    float fx = pred[3 * i + 0],   fy = pred[3 * i + 1],   fz = pred[3 * i + 2];
    float p2x = cx + gx, p2y = cy + gy, p2z = cz + gz;
    float wx  = cx + fx, wy  = cy + fy, wz  = cz + fz;
    g_pc1[i]  = make_float4(cx, cy, cz, cx * cx + cy * cy + cz * cz);
    g_pc2[i]  = make_float4(p2x, p2y, p2z, p2x * p2x + p2y * p2y + p2z * p2z);
    g_warp[i] = make_float4(wx, wy, wz, wx * wx + wy * wy + wz * wz);
    g_flow[i] = make_float4(fx, fy, fz, 0.f);
    atomicAdd(&g_bins[bucketf(cx)], 1);
    atomicAdd(&g_bins[NB + bucketf(p2x)], 1);
    atomicAdd(&g_bins[2 * NB + bucketf(wx)], 1);
}

// exclusive prefix; one block per histogram (grid = 3)
__global__ void scan_kernel() {
    __shared__ int s[NB];
    int t = threadIdx.x;
    int h = blockIdx.x;
    int orig = g_bins[h * NB + t];
    s[t] = orig;
    __syncthreads();
    for (int o = 1; o < NB; o <<= 1) {
        int v = (t >= o) ? s[t - o] : 0;
        __syncthreads();
        s[t] += v;
        __syncthreads();
    }
    g_bins[h * NB + t] = s[t] - orig;  // exclusive start
}

// after this kernel g_bins holds bucket END offsets
__global__ void scatter_kernel(int n) {
    int i = blockIdx.x * blockDim.x + threadIdx.x;
    if (i >= n) return;
    float4 p1 = g_pc1[i];
    int s1 = atomicAdd(&g_bins[bucketf(p1.x)], 1);
    g_p1s[PAD + s1] = p1;
    g_flow1s[PAD + s1] = g_flow[i];
    g_warp1s[PAD + s1] = g_warp[i];
    g_idx1[s1] = i;
    float4 p2 = g_pc2[i];
    int s2 = atomicAdd(&g_bins[NB + bucketf(p2.x)], 1);
    g_p2s[PAD + s2] = p2;
    float4 w = g_warp[i];
    int sw = atomicAdd(&g_bins[2 * NB + bucketf(w.x)], 1);
    g_ws[PAD + sw] = w;
    g_idxw[sw] = i;
}

template <int K>
__device__ __forceinline__ void insert_sorted(float dm, int j,
                                              float (&d)[K], int (&id)[K],
                                              float& kth, float seed) {
    d[K - 1] = dm; id[K - 1] = j;
    #pragma unroll
    for (int s = K - 1; s > 0; --s) {
        if (d[s] < d[s - 1]) {
            float td = d[s]; d[s] = d[s - 1]; d[s - 1] = td;
            int   ti = id[s]; id[s] = id[s - 1]; id[s - 1] = ti;
        }
    }
    kth = fminf(d[K - 1], seed);
}

// Windowed outward scan (one side), seeded kth, per-warp early-skip.
// dm = |p|^2 - 2<q,p>; true = dm + q.w. A warp latches done when ALL its
// lanes' slack-adjusted frontier x-gaps exceed kth_true (nothing beyond can
// enter its top-K); done warps keep loading tiles/hitting barriers but skip
// the inner loop. Block exits when every warp is done or bounds reached.
template <int K>
__device__ __forceinline__ void wscan(const float4* __restrict__ C, float4 q,
                                      int mid, int n, int dir, float4* sp,
                                      float seed, float (&d)[K], int (&id)[K]) {
    #pragma unroll
    for (int t = 0; t < K; t++) { d[t] = 3.4e38f; id[t] = PAD; }
    float kth = seed;
    bool mydone = false;
    if (dir == 0) {
        int j = mid - PTPB;            // mid >= PAD >= PTPB, so j >= 0
        for (;;) {
            __syncthreads();
            sp[threadIdx.x] = C[j + threadIdx.x];
            __syncthreads();
            if (!mydone) {
                #pragma unroll 8
                for (int t = PTPB - 1; t >= 0; --t) {   // near-to-far
                    float4 p = sp[t];
                    float dot = fmaf(q.x, p.x, fmaf(q.y, p.y, q.z * p.z));
                    float dm  = fmaf(-2.f, dot, p.w);
                    if (dm < kth) insert_sorted<K>(dm, j + t, d, id, kth, seed);
                }
            }
            j -= PTPB;
            if (j < 0) break;
            float fx = C[j + PTPB - 1].x;
            float dxm = q.x - fx - BW;
            bool sat = (dxm > 0.f) && (dxm * dxm > kth + q.w);
            mydone = mydone || __all_sync(0xffffffffu, sat);
            if (__syncthreads_and(mydone)) break;
        }
    } else {
        int j = mid;
        const int jend = PAD + n;
        while (j < jend) {
            __syncthreads();
            sp[threadIdx.x] = C[j + threadIdx.x];
            __syncthreads();
            if (!mydone) {
                #pragma unroll 8
                for (int t = 0; t < PTPB; ++t) {        // near-to-far
                    float4 p = sp[t];
                    float dot = fmaf(q.x, p.x, fmaf(q.y, p.y, q.z * p.z));
                    float dm  = fmaf(-2.f, dot, p.w);
                    if (dm < kth) insert_sorted<K>(dm, j + t, d, id, kth, seed);
                }
            }
            j += PTPB;
            if (j >= jend) break;
            float fx = C[j].x;
            float dxm = fx - q.x - BW;
            bool sat = (dxm > 0.f) && (dxm * dxm > kth + q.w);
            mydone = mydone || __all_sync(0xffffffffu, sat);
            if (__syncthreads_and(mydone)) break;
        }
    }
}

// min-only variant (reverse chamfer), per-warp early-skip
__device__ __forceinline__ float wmin(const float4* __restrict__ C, float4 q,
                                      int mid, int n, int dir, float4* sp) {
    float m = 3.4e38f;
    bool mydone = false;
    if (dir == 0) {
        int j = mid - PTPB;
        for (;;) {
            __syncthreads();
            sp[threadIdx.x] = C[j + threadIdx.x];
            __syncthreads();
            if (!mydone) {
                #pragma unroll 8
                for (int t = PTPB - 1; t >= 0; --t) {
                    float4 p = sp[t];
                    float dot = fmaf(q.x, p.x, fmaf(q.y, p.y, q.z * p.z));
                    m = fminf(m, fmaf(-2.f, dot, p.w));
                }
            }
            j -= PTPB;
            if (j < 0) break;
            float fx = C[j + PTPB - 1].x;
            float dxm = q.x - fx - BW;
            bool sat = (dxm > 0.f) && (dxm * dxm > m + q.w);
            mydone = mydone || __all_sync(0xffffffffu, sat);
            if (__syncthreads_and(mydone)) break;
        }
    } else {
        int j = mid;
        const int jend = PAD + n;
        while (j < jend) {
            __syncthreads();
            sp[threadIdx.x] = C[j + threadIdx.x];
            __syncthreads();
            if (!mydone) {
                #pragma unroll 8
                for (int t = 0; t < PTPB; ++t) {
                    float4 p = sp[t];
                    float dot = fmaf(q.x, p.x, fmaf(q.y, p.y, q.z * p.z));
                    m = fminf(m, fmaf(-2.f, dot, p.w));
                }
            }
            j += PTPB;
            if (j >= jend) break;
            float fx = C[j].x;
            float dxm = fx - q.x - BW;
            bool sat = (dxm > 0.f) && (dxm * dxm > m + q.w);
            mydone = mydone || __all_sync(0xffffffffu, sat);
            if (__syncthreads_and(mydone)) break;
        }
    }
    return m;
}

// grid = (n/PTPB, 2, 4): y = side, z = slice. Seeds computed inline.
__global__ void __launch_bounds__(PTPB) pairs_kernel(int n, const int* __restrict__ kptr) {
    __shared__ float4 sp[PTPB];
    const int slice = blockIdx.z;
    const int dir = blockIdx.y;
    const int qbase = blockIdx.x * PTPB;
    const int i = qbase + threadIdx.x;

    const float4* __restrict__ Q;
    const float4* __restrict__ C;
    int hc;
    if      (slice == 0) { Q = g_p2s; C = g_p2s; hc = 1; }
    else if (slice == 1) { Q = g_p1s; C = g_p1s; hc = 0; }
    else if (slice == 2) { Q = g_ws;  C = g_p2s; hc = 1; }
    else                 { Q = g_p2s; C = g_ws;  hc = 2; }

    float4 q = Q[PAD + i];
    float xmed = Q[PAD + qbase + PTPB / 2].x;
    int mid = PAD + g_bins[hc * NB + bucketf(xmed)];

    if (slice <= 2) {
        // inline seed: max dm over >=K nearby sorted candidates (upper bound on
        // true kth), bumped so the seed-defining candidate passes strict '<'.
        float mx = -3.4e38f;
        if (slice < 2) {
            #pragma unroll
            for (int t = -5; t <= 5; t++) {
                if (t == 0) continue;
                float4 p = C[PAD + i + t];
                float dot = fmaf(q.x, p.x, fmaf(q.y, p.y, q.z * p.z));
                float dm  = fmaf(-2.f, dot, p.w);
                mx = fmaxf(mx, dm);
            }
        } else {
            int pos = g_bins[NB + bucketf(q.x)];   // bucket end in p2s order
            #pragma unroll
            for (int t = -3; t <= 2; t++) {
                float4 p = g_p2s[PAD + pos + t];
                float dot = fmaf(q.x, p.x, fmaf(q.y, p.y, q.z * p.z));
                float dm  = fmaf(-2.f, dot, p.w);
                mx = fmaxf(mx, dm);
            }
        }
        float seed = mx + fabsf(mx) * 1e-6f + 1e-30f;

        if (slice < 2) {
            float d[KNN]; int id[KNN];
            wscan<KNN>(C, q, mid, n, dir, sp, seed, d, id);
            int b = ((slice * MAXN + i) * 2 + dir) * KNN;
            #pragma unroll
            for (int t = 0; t < KNN; t++) { g_pd[b + t] = d[t] + q.w; g_pi[b + t] = id[t]; }
        } else {
            float d[KNN5]; int id[KNN5];
            wscan<KNN5>(C, q, mid, n, dir, sp, seed, d, id);
            int b = ((2 * MAXN + i) * 2 + dir) * KNN;
            #pragma unroll
            for (int t = 0; t < KNN5; t++) { g_pd[b + t] = d[t] + q.w; g_pi[b + t] = id[t]; }
        }
    } else {
        float m = wmin(C, q, mid, n, dir, sp);
        g_pmin[i * 2 + dir] = m + q.w;
    }
}

// Stable 2-chunk merge (true distances, strict '<'); sentinels never win.
template <int K>
__device__ __forceinline__ void merge_topk(int r, int i, float (&d)[K], int (&id)[K]) {
    #pragma unroll
    for (int t = 0; t < K; t++) { d[t] = 3.4e38f; id[t] = PAD; }
    int base = (r * MAXN + i) * 2 * KNN;
    #pragma unroll
    for (int c = 0; c < 2; c++) {
        #pragma unroll
        for (int t = 0; t < K; t++) {
            float dist = g_pd[base + c * KNN + t];
            int j = g_pi[base + c * KNN + t];
            if (dist < d[K - 1]) {
                d[K - 1] = dist; id[K - 1] = j;
                #pragma unroll
                for (int s = K - 1; s > 0; --s) {
                    if (d[s] < d[s - 1]) {
                        float td = d[s]; d[s] = d[s - 1]; d[s - 1] = td;
                        int   ti = id[s]; id[s] = id[s - 1]; id[s - 1] = ti;
                    }
                }
            }
        }
    }
}

// grid.y: 0 = c2 curvature, 1 = moved curvature + smoothness, 2 = reverse chamfer
__global__ void consumeA_kernel(int n, const int* __restrict__ kptr) {
    int i = blockIdx.x * blockDim.x + threadIdx.x;
    int task = blockIdx.y;
    if (task == 0) {
        if (i >= n) return;
        float d[KNN]; int id[KNN];
        merge_topk<KNN>(0, i, d, id);
        float4 qq = g_p2s[PAD + i];
        float sx = 0.f, sy = 0.f, sz = 0.f;
        #pragma unroll
        for (int t = 0; t < KNN; t++) {
            float4 p = g_p2s[id[t]];
            sx += p.x; sy += p.y; sz += p.z;
        }
        g_c2s[PAD + i] = make_float4((sx - 10.f * qq.x) / 9.f,
                                     (sy - 10.f * qq.y) / 9.f,
                                     (sz - 10.f * qq.z) / 9.f, 0.f);
    } else if (task == 1) {
        double sm_d = 0.0;
        if (i < n) {
            float d[KNN]; int id[KNN];
            merge_topk<KNN>(1, i, d, id);
            float4 w = g_warp1s[PAD + i];
            float sx = 0.f, sy = 0.f, sz = 0.f;
            #pragma unroll
            for (int t = 0; t < KNN; t++) {
                float4 p = g_warp1s[id[t]];
                sx += p.x; sy += p.y; sz += p.z;
            }
            g_moved[g_idx1[i]] = make_float4((sx - 10.f * w.x) / 9.f,
                                             (sy - 10.f * w.y) / 9.f,
                                             (sz - 10.f * w.z) / 9.f, 0.f);
            int k = *kptr;
            float4 f = g_flow1s[PAD + i];
            float sm = 0.f;
            #pragma unroll
            for (int t = 0; t < KNN; t++) {
                if (t < k) {
                    float4 gfl = g_flow1s[id[t]];
                    float dx = gfl.x - f.x, dy = gfl.y - f.y, dz = gfl.z - f.z;
                    float sq = dx * dx + dy * dy + dz * dz;
                    sm += sqrtf(sq);   // sq==0 (self) -> 0, matches safe-norm
                }
            }
            sm_d = (double)(sm / 8.f);
        }
        double v = warp_red(sm_d);
        if ((threadIdx.x & 31) == 0) atomicAdd(&g_acc[2], v);
    } else {
        double v = 0.0;
        if (i < n) v = (double)fminf(g_pmin[i * 2], g_pmin[i * 2 + 1]);
        double s = warp_red(v);
        if ((threadIdx.x & 31) == 0) atomicAdd(&g_acc[1], s);
    }
}

// warp->pc2 top-5 merge -> chamfer fwd + interp-curvature; last block finalizes.
__global__ void cross_consume_kernel(int n, float* __restrict__ out) {
    int i = blockIdx.x * blockDim.x + threadIdx.x;
    double d1 = 0.0, cv = 0.0;
    if (i < n) {
        float d[KNN5]; int id[KNN5];
        merge_topk<KNN5>(2, i, d, id);
        d1 = (double)d[0];
        float w[KNN5]; float wsum = 0.f;
        #pragma unroll
        for (int t = 0; t < KNN5; t++) { w[t] = 1.f / (d[t] + 1e-8f); wsum += w[t]; }
        float ix = 0.f, iy = 0.f, iz = 0.f;
        #pragma unroll
        for (int t = 0; t < KNN5; t++) {
            float wn = w[t] / wsum;
            float4 c = g_c2s[id[t]];
            ix = fmaf(wn, c.x, ix);
            iy = fmaf(wn, c.y, iy);
            iz = fmaf(wn, c.z, iz);
        }
        float4 m = g_moved[g_idxw[i]];
        float ex = ix - m.x, ey = iy - m.y, ez = iz - m.z;
        cv = (double)(ex * ex + ey * ey + ez * ez);
    }
    double v0 = warp_red(d1);
    double v1 = warp_red(cv);
    if ((threadIdx.x & 31) == 0) {
        atomicAdd(&g_acc[0], v0);
        atomicAdd(&g_acc[3], v1);
    }
    __threadfence();
    __syncthreads();
    if (threadIdx.x == 0) {
        int t = atomicAdd(&g_ticket, 1);
        if (t == (int)gridDim.x - 1) {
            __threadfence();
            double a0 = *((volatile double*)&g_acc[0]);
            double a1 = *((volatile double*)&g_acc[1]);
            double a2 = *((volatile double*)&g_acc[2]);
            double a3 = *((volatile double*)&g_acc[3]);
            out[0] = (float)(0.02 * (a0 + a1) + 0.006 * a3 + 0.01 * a2);
        }
    }
}

extern "C" void kernel_launch(void* const* d_in, const int* in_sizes, int n_in,
                              void* d_out, int out_size) {
    const float* pred   = (const float*)d_in[0];  // registration_pred (1,N,3)
    const float* gt     = (const float*)d_in[1];  // registration_gt   (1,N,3)
    const float* coords = (const float*)d_in[2];  // coords            (N,3)
    const int*   kptr   = (const int*)d_in[3];    // smoothness_k

    int n = in_sizes[2] / 3;   // 8192
    int cb = (n + 255) / 256;

    zero_kernel<<<3, 1024>>>();
    prep_kernel<<<cb, 256>>>(pred, gt, coords, n);
    scan_kernel<<<3, NB>>>();
    scatter_kernel<<<cb, 256>>>(n);
    pairs_kernel<<<dim3(n / PTPB, 2, 4), PTPB>>>(n, kptr);
    consumeA_kernel<<<dim3(cb, 3), 256>>>(n, kptr);
    cross_consume_kernel<<<cb, 256>>>(n, (float*)d_out);
}